// round 11
// baseline (speedup 1.0000x reference)
#include <cuda_runtime.h>
#include <math.h>

// Problem dims
#define SEQLEN 8192
#define INSZ   512
#define HSZ    2048
#define OSZ    512

// Recurrence: 128 CTAs x 16 rows. Warp w (0..7) owns rows 2w, 2w+1.
// Lane l covers h/W elements 128j+4l..+3 (coalesced float4).
#define NCTA 128
#define RPC  16

// Scratch (device globals: allocation-free rule)
__device__ float    g_A[(size_t)SEQLEN * HSZ];         // U x_t + U_b ; reused as Z
__device__ float    g_Hst[(size_t)(SEQLEN + 1) * HSZ]; // h_0 .. h_8192
__device__ unsigned g_ctr;                             // fallback release counter

// ---------------------------------------------------------------------------
// PTX helpers
// ---------------------------------------------------------------------------
static __device__ __forceinline__ unsigned ld_acq(const unsigned* p) {
    unsigned v;
    asm volatile("ld.acquire.gpu.global.u32 %0, [%1];" : "=r"(v) : "l"(p));
    return v;
}
static __device__ __forceinline__ void red_rel_add(unsigned* p, unsigned v) {
    asm volatile("red.release.gpu.global.add.u32 [%0], %1;" :: "l"(p), "r"(v));
}
// L1-bypassing float4 load (L2-coherent) — used for the post-wait reload,
// where the speculative load may have cached a stale NaN line in L1.
static __device__ __forceinline__ float4 ldcg4(const float4* p) {
    float4 v;
    asm volatile("ld.global.cg.v4.f32 {%0,%1,%2,%3}, [%4];"
                 : "=f"(v.x), "=f"(v.y), "=f"(v.z), "=f"(v.w) : "l"(p));
    return v;
}
// packed f32x2 FMA: acc.{lo,hi} += a*b  (Blackwell; 2x fp32 rate)
static __device__ __forceinline__ void fma2(unsigned long long& acc,
                                            float a0, float a1, float b0, float b1) {
    asm("{\n\t"
        ".reg .b64 ta, tb;\n\t"
        "mov.b64 ta, {%1, %2};\n\t"
        "mov.b64 tb, {%3, %4};\n\t"
        "fma.rn.f32x2 %0, ta, tb, %0;\n\t"
        "}"
        : "+l"(acc) : "f"(a0), "f"(a1), "f"(b0), "f"(b1));
}
static __device__ __forceinline__ float unpack_sum(unsigned long long acc) {
    float lo, hi;
    asm("mov.b64 {%0, %1}, %2;" : "=f"(lo), "=f"(hi) : "l"(acc));
    return lo + hi;
}
// tanh(x) = 1 - 2/(e^{2x}+1): MUFU ex2 + approx div (validated rel_err 1.1e-6)
static __device__ __forceinline__ float fast_tanh(float x) {
    float e = __expf(2.f * x);
    return 1.f - __fdividef(2.f, e + 1.f);
}

// ---------------------------------------------------------------------------
// Init: reset counter, load h_0; poison rows 1..SEQLEN with NaN sentinel
// ---------------------------------------------------------------------------
__global__ void init_k(const float* __restrict__ hidden) {
    int i = blockIdx.x * blockDim.x + threadIdx.x;
    if (i == 0) g_ctr = 0;
    if (i < HSZ) g_Hst[i] = hidden[i];
}
__global__ void poison_k() {
    size_t idx = (size_t)blockIdx.x * blockDim.x + threadIdx.x;
    const float qnan = __int_as_float(0x7fc00000);
    ((float4*)(g_Hst + HSZ))[idx] = make_float4(qnan, qnan, qnan, qnan);
}

// ---------------------------------------------------------------------------
// SGEMM: C[M,N] = A[M,K] * B[N,K]^T + bias[N]   (row-major)
// ---------------------------------------------------------------------------
__global__ __launch_bounds__(256) void sgemm_tn_bias(
    const float* __restrict__ A, const float* __restrict__ B,
    const float* __restrict__ bias, float* __restrict__ C,
    int M, int N, int K)
{
    __shared__ float As[8][128];
    __shared__ float Bs[8][128];
    const int tid  = threadIdx.x;
    const int tx   = tid & 15;
    const int ty   = tid >> 4;
    const int lrow = tid >> 1;
    const int lcol = (tid & 1) * 4;

    const float* Ap = A + (size_t)(blockIdx.y * 128 + lrow) * K + lcol;
    const float* Bp = B + (size_t)(blockIdx.x * 128 + lrow) * K + lcol;

    float acc[8][8];
    #pragma unroll
    for (int i = 0; i < 8; ++i)
        #pragma unroll
        for (int j = 0; j < 8; ++j) acc[i][j] = 0.f;

    for (int k0 = 0; k0 < K; k0 += 8) {
        float4 a4 = *(const float4*)(Ap + k0);
        float4 b4 = *(const float4*)(Bp + k0);
        As[lcol + 0][lrow] = a4.x; As[lcol + 1][lrow] = a4.y;
        As[lcol + 2][lrow] = a4.z; As[lcol + 3][lrow] = a4.w;
        Bs[lcol + 0][lrow] = b4.x; Bs[lcol + 1][lrow] = b4.y;
        Bs[lcol + 2][lrow] = b4.z; Bs[lcol + 3][lrow] = b4.w;
        __syncthreads();
        #pragma unroll
        for (int k = 0; k < 8; ++k) {
            float ar[8], br[8];
            *(float4*)&ar[0] = *(const float4*)&As[k][ty * 8];
            *(float4*)&ar[4] = *(const float4*)&As[k][ty * 8 + 4];
            *(float4*)&br[0] = *(const float4*)&Bs[k][tx * 8];
            *(float4*)&br[4] = *(const float4*)&Bs[k][tx * 8 + 4];
            #pragma unroll
            for (int i = 0; i < 8; ++i)
                #pragma unroll
                for (int j = 0; j < 8; ++j)
                    acc[i][j] = fmaf(ar[i], br[j], acc[i][j]);
        }
        __syncthreads();
    }

    const int cm = blockIdx.y * 128 + ty * 8;
    const int cn = blockIdx.x * 128 + tx * 8;
    float bv[8];
    #pragma unroll
    for (int j = 0; j < 8; ++j) bv[j] = bias[cn + j];
    #pragma unroll
    for (int i = 0; i < 8; ++i) {
        float4 o0, o1;
        o0.x = acc[i][0] + bv[0]; o0.y = acc[i][1] + bv[1];
        o0.z = acc[i][2] + bv[2]; o0.w = acc[i][3] + bv[3];
        o1.x = acc[i][4] + bv[4]; o1.y = acc[i][5] + bv[5];
        o1.z = acc[i][6] + bv[6]; o1.w = acc[i][7] + bv[7];
        *(float4*)(C + (size_t)(cm + i) * N + cn)     = o0;
        *(float4*)(C + (size_t)(cm + i) * N + cn + 4) = o1;
    }
}

// ---------------------------------------------------------------------------
// Persistent recurrence (R8 layout + NaN-sentinel speculation):
//   h_{i+1} = tanh(A[i] + W h_i + W_b)
// Fast path: speculative cached loads of h_i; if the warp's whole slice is
// non-NaN, consume immediately — no sync at all. Fallback: ONE converged
// counter wait (R2-proven primitive) + ONE ld.cg reload. Counter is bumped
// once per CTA per step (trailing bar + red.release.add), so the fallback
// always terminates.
// ---------------------------------------------------------------------------
__global__ __launch_bounds__(256, 1) void rnn_recur(
    const float* __restrict__ W, const float* __restrict__ Wb)
{
    const int tid  = threadIdx.x;
    const int cta  = blockIdx.x;
    const int warp = tid >> 5;     // 0..7
    const int lane = tid & 31;
    const int grow0 = cta * RPC + 2 * warp;      // this warp's first row

    // W slices in registers: rows grow0, grow0+1; lane l holds float4 j at
    // element offset 128j+4l (matches coalesced h load pattern).
    float4 w0[16], w1[16];
    {
        const float4* W0 = (const float4*)(W + (size_t)grow0 * HSZ);
        const float4* W1 = (const float4*)(W + (size_t)(grow0 + 1) * HSZ);
        #pragma unroll
        for (int j = 0; j < 16; ++j) { w0[j] = W0[32 * j + lane]; w1[j] = W1[32 * j + lane]; }
    }
    float2 wb = make_float2(0.f, 0.f);
    if (lane == 0) wb = *(const float2*)(Wb + grow0);

    for (int i = 0; i < SEQLEN; ++i) {
        // Prefetch A pair (sync-independent)
        float2 av = make_float2(0.f, 0.f);
        if (lane == 0) av = *(const float2*)(g_A + (size_t)i * HSZ + grow0);

        const float4* hp = (const float4*)(g_Hst + (size_t)i * HSZ);
        float4 hb[16];

        // Speculative cached loads (fresh addresses -> L1 miss -> L2-coherent;
        // later warps of this CTA get L1 hits on the same lines).
        #pragma unroll
        for (int j = 0; j < 16; ++j) hb[j] = hp[32 * j + lane];

        // NaN-propagating validity checksum over this lane's 64 values
        float t = 0.f;
        #pragma unroll
        for (int j = 0; j < 16; ++j)
            t += (hb[j].x + hb[j].y) + (hb[j].z + hb[j].w);

        if (!__all_sync(0xffffffffu, t == t)) {
            // Fallback: wait until all CTAs published h_i, then reload fresh
            // (ld.cg bypasses the possibly-stale-NaN L1 lines).
            const unsigned target = (unsigned)i * NCTA;
            while (ld_acq(&g_ctr) < target) { }
            #pragma unroll
            for (int j = 0; j < 16; ++j) hb[j] = ldcg4(hp + 32 * j + lane);
        }

        // Dual-row packed FMA
        unsigned long long a0 = 0ull, b0 = 0ull, a1 = 0ull, b1 = 0ull;
        #pragma unroll
        for (int j = 0; j < 16; ++j) {
            fma2(a0, hb[j].x, hb[j].y, w0[j].x, w0[j].y);
            fma2(b0, hb[j].z, hb[j].w, w0[j].z, w0[j].w);
            fma2(a1, hb[j].x, hb[j].y, w1[j].x, w1[j].y);
            fma2(b1, hb[j].z, hb[j].w, w1[j].z, w1[j].w);
        }
        float p0 = unpack_sum(a0) + unpack_sum(b0);
        float p1 = unpack_sum(a1) + unpack_sum(b1);

        // Warp-local butterfly reduction: two independent chains, ILP overlap
        #pragma unroll
        for (int o = 16; o > 0; o >>= 1) {
            p0 += __shfl_xor_sync(0xffffffffu, p0, o);
            p1 += __shfl_xor_sync(0xffffffffu, p1, o);
        }

        // Lane 0 of each warp: tanh + store its row pair (the store IS the
        // fast-path notification; tanh output is never NaN)
        if (lane == 0) {
            float h0 = fast_tanh(p0 + av.x + wb.x);
            float h1 = fast_tanh(p1 + av.y + wb.y);
            *(float2*)(g_Hst + (size_t)(i + 1) * HSZ + grow0) = make_float2(h0, h1);
        }
        __syncthreads();          // all 16 rows stored before the counter bump
        if (tid == 0) red_rel_add(&g_ctr, 1u);   // fallback-path publish
    }
}

// ---------------------------------------------------------------------------
// log_softmax over rows of Z [SEQLEN, OSZ], one warp per row
// ---------------------------------------------------------------------------
__global__ __launch_bounds__(128) void logsoftmax_k(
    const float* __restrict__ Z, float* __restrict__ Y)
{
    int warp = (blockIdx.x * blockDim.x + threadIdx.x) >> 5;
    int lane = threadIdx.x & 31;
    if (warp >= SEQLEN) return;
    const float* z = Z + (size_t)warp * OSZ;
    float v[16];
    float m = -INFINITY;
    #pragma unroll
    for (int j = 0; j < 16; ++j) {
        v[j] = z[lane + 32 * j];
        m = fmaxf(m, v[j]);
    }
    #pragma unroll
    for (int o = 16; o > 0; o >>= 1) m = fmaxf(m, __shfl_xor_sync(~0u, m, o));
    float s = 0.f;
    #pragma unroll
    for (int j = 0; j < 16; ++j) s += __expf(v[j] - m);
    #pragma unroll
    for (int o = 16; o > 0; o >>= 1) s += __shfl_xor_sync(~0u, s, o);
    float lse = m + __logf(s);
    float* y = Y + (size_t)warp * OSZ;
    #pragma unroll
    for (int j = 0; j < 16; ++j) y[lane + 32 * j] = v[j] - lse;
}

__global__ void copy_hfinal(float* __restrict__ out) {
    int i = blockIdx.x * blockDim.x + threadIdx.x;
    if (i < HSZ) out[i] = g_Hst[(size_t)SEQLEN * HSZ + i];
}

// ---------------------------------------------------------------------------
// kernel_launch
// Inputs: 0 input[8192,512] 1 hidden[1,2048] 2 U_w[2048,512] 3 U_b[2048]
//         4 W_w[2048,2048]  5 W_b[2048]      6 V_w[512,2048]  7 V_b[512]
// Output: y[8192,512] ++ h_final[2048]
// ---------------------------------------------------------------------------
extern "C" void kernel_launch(void* const* d_in, const int* in_sizes, int n_in,
                              void* d_out, int out_size)
{
    (void)in_sizes; (void)n_in; (void)out_size;
    const float* input  = (const float*)d_in[0];
    const float* hidden = (const float*)d_in[1];
    const float* U_w    = (const float*)d_in[2];
    const float* U_b    = (const float*)d_in[3];
    const float* W_w    = (const float*)d_in[4];
    const float* W_b    = (const float*)d_in[5];
    const float* V_w    = (const float*)d_in[6];
    const float* V_b    = (const float*)d_in[7];
    float* out = (float*)d_out;

    float *pA, *pH;
    cudaGetSymbolAddress((void**)&pA, g_A);
    cudaGetSymbolAddress((void**)&pH, g_Hst);

    // 1) reset counter + h_0; re-poison rows 1..SEQLEN (every graph replay)
    init_k<<<8, 256>>>(hidden);
    poison_k<<<(SEQLEN * HSZ / 4) / 256, 256>>>();

    // 2) A = X U^T + U_b : [8192,2048]
    sgemm_tn_bias<<<dim3(HSZ / 128, SEQLEN / 128), 256>>>(
        input, U_w, U_b, pA, SEQLEN, HSZ, INSZ);

    // 3) sequential recurrence -> g_Hst rows 1..8192
    rnn_recur<<<NCTA, 256>>>(W_w, W_b);

    // 4) Z = H V^T + V_b : [8192,512]  (reuse g_A as Z; H rows 1..8192)
    sgemm_tn_bias<<<dim3(OSZ / 128, SEQLEN / 128), 256>>>(
        pH + HSZ, V_w, V_b, pA, SEQLEN, OSZ, HSZ);

    // 5) y = log_softmax(Z) ; h_final
    logsoftmax_k<<<SEQLEN / 4, 128>>>(pA, out);
    copy_hfinal<<<8, 256>>>(out + (size_t)SEQLEN * OSZ);
}

// round 14
// speedup vs baseline: 3.0670x; 3.0670x over previous
#include <cuda_runtime.h>
#include <math.h>

// Problem dims
#define SEQLEN 8192
#define INSZ   512
#define HSZ    2048
#define OSZ    512

// Recurrence: 128 CTAs x 16 rows, 256 threads. Warp w (0..7) owns rows
// 2w, 2w+1. Lane l covers h/W elements 128j+4l..+3 (coalesced float4).
// Register budget: 2x16 float4 W (128) + 8 float4 h chunk (32) + accums
// fits 256 thr x 256 regs with headroom (R8 spilled at 254).
#define NCTA 128
#define RPC  16

// Scratch (device globals: allocation-free rule)
__device__ float    g_A[(size_t)SEQLEN * HSZ];         // U x_t + U_b ; reused as Z
__device__ float    g_Hst[(size_t)(SEQLEN + 1) * HSZ]; // h_0 .. h_8192
__device__ unsigned g_ctr;                             // single release counter

// ---------------------------------------------------------------------------
// PTX helpers
// ---------------------------------------------------------------------------
static __device__ __forceinline__ unsigned ld_acq(const unsigned* p) {
    unsigned v;
    asm volatile("ld.acquire.gpu.global.u32 %0, [%1];" : "=r"(v) : "l"(p));
    return v;
}
static __device__ __forceinline__ void red_rel_add(unsigned* p, unsigned v) {
    asm volatile("red.release.gpu.global.add.u32 [%0], %1;" :: "l"(p), "r"(v));
}
// packed f32x2 FMA: acc.{lo,hi} += a*b  (Blackwell; 2x fp32 rate)
static __device__ __forceinline__ void fma2(unsigned long long& acc,
                                            float a0, float a1, float b0, float b1) {
    asm("{\n\t"
        ".reg .b64 ta, tb;\n\t"
        "mov.b64 ta, {%1, %2};\n\t"
        "mov.b64 tb, {%3, %4};\n\t"
        "fma.rn.f32x2 %0, ta, tb, %0;\n\t"
        "}"
        : "+l"(acc) : "f"(a0), "f"(a1), "f"(b0), "f"(b1));
}
static __device__ __forceinline__ float unpack_sum(unsigned long long acc) {
    float lo, hi;
    asm("mov.b64 {%0, %1}, %2;" : "=f"(lo), "=f"(hi) : "l"(acc));
    return lo + hi;
}
// tanh(x) = 1 - 2/(e^{2x}+1): MUFU ex2 + approx div (validated rel_err 1.1e-6)
static __device__ __forceinline__ float fast_tanh(float x) {
    float e = __expf(2.f * x);
    return 1.f - __fdividef(2.f, e + 1.f);
}

// ---------------------------------------------------------------------------
// Init: reset counter, load h_0
// ---------------------------------------------------------------------------
__global__ void init_k(const float* __restrict__ hidden) {
    int i = blockIdx.x * blockDim.x + threadIdx.x;
    if (i == 0) g_ctr = 0;
    if (i < HSZ) g_Hst[i] = hidden[i];
}

// ---------------------------------------------------------------------------
// SGEMM: C[M,N] = A[M,K] * B[N,K]^T + bias[N]   (row-major)
// ---------------------------------------------------------------------------
__global__ __launch_bounds__(256) void sgemm_tn_bias(
    const float* __restrict__ A, const float* __restrict__ B,
    const float* __restrict__ bias, float* __restrict__ C,
    int M, int N, int K)
{
    __shared__ float As[8][128];
    __shared__ float Bs[8][128];
    const int tid  = threadIdx.x;
    const int tx   = tid & 15;
    const int ty   = tid >> 4;
    const int lrow = tid >> 1;
    const int lcol = (tid & 1) * 4;

    const float* Ap = A + (size_t)(blockIdx.y * 128 + lrow) * K + lcol;
    const float* Bp = B + (size_t)(blockIdx.x * 128 + lrow) * K + lcol;

    float acc[8][8];
    #pragma unroll
    for (int i = 0; i < 8; ++i)
        #pragma unroll
        for (int j = 0; j < 8; ++j) acc[i][j] = 0.f;

    for (int k0 = 0; k0 < K; k0 += 8) {
        float4 a4 = *(const float4*)(Ap + k0);
        float4 b4 = *(const float4*)(Bp + k0);
        As[lcol + 0][lrow] = a4.x; As[lcol + 1][lrow] = a4.y;
        As[lcol + 2][lrow] = a4.z; As[lcol + 3][lrow] = a4.w;
        Bs[lcol + 0][lrow] = b4.x; Bs[lcol + 1][lrow] = b4.y;
        Bs[lcol + 2][lrow] = b4.z; Bs[lcol + 3][lrow] = b4.w;
        __syncthreads();
        #pragma unroll
        for (int k = 0; k < 8; ++k) {
            float ar[8], br[8];
            *(float4*)&ar[0] = *(const float4*)&As[k][ty * 8];
            *(float4*)&ar[4] = *(const float4*)&As[k][ty * 8 + 4];
            *(float4*)&br[0] = *(const float4*)&Bs[k][tx * 8];
            *(float4*)&br[4] = *(const float4*)&Bs[k][tx * 8 + 4];
            #pragma unroll
            for (int i = 0; i < 8; ++i)
                #pragma unroll
                for (int j = 0; j < 8; ++j)
                    acc[i][j] = fmaf(ar[i], br[j], acc[i][j]);
        }
        __syncthreads();
    }

    const int cm = blockIdx.y * 128 + ty * 8;
    const int cn = blockIdx.x * 128 + tx * 8;
    float bv[8];
    #pragma unroll
    for (int j = 0; j < 8; ++j) bv[j] = bias[cn + j];
    #pragma unroll
    for (int i = 0; i < 8; ++i) {
        float4 o0, o1;
        o0.x = acc[i][0] + bv[0]; o0.y = acc[i][1] + bv[1];
        o0.z = acc[i][2] + bv[2]; o0.w = acc[i][3] + bv[3];
        o1.x = acc[i][4] + bv[4]; o1.y = acc[i][5] + bv[5];
        o1.z = acc[i][6] + bv[6]; o1.w = acc[i][7] + bv[7];
        *(float4*)(C + (size_t)(cm + i) * N + cn)     = o0;
        *(float4*)(C + (size_t)(cm + i) * N + cn + 4) = o1;
    }
}

// ---------------------------------------------------------------------------
// Persistent recurrence: h_{i+1} = tanh(A[i] + W h_i + W_b)
// R8's proven structure exactly (tid0 poll -> bar -> compute -> bar -> tid0
// release). ONE change vs R8: h loads chunked 2x8 float4, FMA interleaved,
// cutting ~32 live registers to clear the 254-reg spill cliff.
// ---------------------------------------------------------------------------
__global__ __launch_bounds__(256, 1) void rnn_recur(
    const float* __restrict__ W, const float* __restrict__ Wb)
{
    const int tid  = threadIdx.x;
    const int cta  = blockIdx.x;
    const int warp = tid >> 5;     // 0..7
    const int lane = tid & 31;
    const int grow0 = cta * RPC + 2 * warp;      // this warp's first row

    // W slices in registers: rows grow0, grow0+1; lane l holds float4 j at
    // element offset 128j+4l (matches coalesced h load pattern).
    float4 w0[16], w1[16];
    {
        const float4* W0 = (const float4*)(W + (size_t)grow0 * HSZ);
        const float4* W1 = (const float4*)(W + (size_t)(grow0 + 1) * HSZ);
        #pragma unroll
        for (int j = 0; j < 16; ++j) { w0[j] = W0[32 * j + lane]; w1[j] = W1[32 * j + lane]; }
    }
    float2 wb = make_float2(0.f, 0.f);
    if (lane == 0) wb = *(const float2*)(Wb + grow0);

    for (int i = 0; i < SEQLEN; ++i) {
        // Prefetch A pair (counter-independent) — hides DRAM under the wait
        float2 av = make_float2(0.f, 0.f);
        if (lane == 0) av = *(const float2*)(g_A + (size_t)i * HSZ + grow0);

        // Wait for all CTAs to have published h_i (single counter, tid0 only)
        if (i > 0) {
            if (tid == 0) {
                const unsigned target = (unsigned)i * NCTA;
                while (ld_acq(&g_ctr) < target) { }
            }
            __syncthreads();
        }

        // Coalesced h loads, 2 chunks of 8 float4 (MLP=8, low reg pressure),
        // FMAs interleaved per chunk.
        const float4* hp = (const float4*)(g_Hst + (size_t)i * HSZ);
        unsigned long long a0 = 0ull, b0 = 0ull, a1 = 0ull, b1 = 0ull;
        #pragma unroll
        for (int c = 0; c < 2; ++c) {
            float4 hb[8];
            #pragma unroll
            for (int j = 0; j < 8; ++j) hb[j] = hp[32 * (c * 8 + j) + lane];
            #pragma unroll
            for (int j = 0; j < 8; ++j) {
                const int idx = c * 8 + j;
                fma2(a0, hb[j].x, hb[j].y, w0[idx].x, w0[idx].y);
                fma2(b0, hb[j].z, hb[j].w, w0[idx].z, w0[idx].w);
                fma2(a1, hb[j].x, hb[j].y, w1[idx].x, w1[idx].y);
                fma2(b1, hb[j].z, hb[j].w, w1[idx].z, w1[idx].w);
            }
        }
        float p0 = unpack_sum(a0) + unpack_sum(b0);
        float p1 = unpack_sum(a1) + unpack_sum(b1);

        // Warp-local butterfly reduction: two independent chains, ILP overlap
        #pragma unroll
        for (int o = 16; o > 0; o >>= 1) {
            p0 += __shfl_xor_sync(0xffffffffu, p0, o);
            p1 += __shfl_xor_sync(0xffffffffu, p1, o);
        }

        // Lane 0 of each warp: tanh + store its row pair
        if (lane == 0) {
            float h0 = fast_tanh(p0 + av.x + wb.x);
            float h1 = fast_tanh(p1 + av.y + wb.y);
            *(float2*)(g_Hst + (size_t)(i + 1) * HSZ + grow0) = make_float2(h0, h1);
        }
        __syncthreads();          // all 16 rows of this CTA stored
        if (tid == 0) red_rel_add(&g_ctr, 1u);   // publish
    }
}

// ---------------------------------------------------------------------------
// log_softmax over rows of Z [SEQLEN, OSZ], one warp per row
// ---------------------------------------------------------------------------
__global__ __launch_bounds__(128) void logsoftmax_k(
    const float* __restrict__ Z, float* __restrict__ Y)
{
    int warp = (blockIdx.x * blockDim.x + threadIdx.x) >> 5;
    int lane = threadIdx.x & 31;
    if (warp >= SEQLEN) return;
    const float* z = Z + (size_t)warp * OSZ;
    float v[16];
    float m = -INFINITY;
    #pragma unroll
    for (int j = 0; j < 16; ++j) {
        v[j] = z[lane + 32 * j];
        m = fmaxf(m, v[j]);
    }
    #pragma unroll
    for (int o = 16; o > 0; o >>= 1) m = fmaxf(m, __shfl_xor_sync(~0u, m, o));
    float s = 0.f;
    #pragma unroll
    for (int j = 0; j < 16; ++j) s += __expf(v[j] - m);
    #pragma unroll
    for (int o = 16; o > 0; o >>= 1) s += __shfl_xor_sync(~0u, s, o);
    float lse = m + __logf(s);
    float* y = Y + (size_t)warp * OSZ;
    #pragma unroll
    for (int j = 0; j < 16; ++j) y[lane + 32 * j] = v[j] - lse;
}

__global__ void copy_hfinal(float* __restrict__ out) {
    int i = blockIdx.x * blockDim.x + threadIdx.x;
    if (i < HSZ) out[i] = g_Hst[(size_t)SEQLEN * HSZ + i];
}

// ---------------------------------------------------------------------------
// kernel_launch
// Inputs: 0 input[8192,512] 1 hidden[1,2048] 2 U_w[2048,512] 3 U_b[2048]
//         4 W_w[2048,2048]  5 W_b[2048]      6 V_w[512,2048]  7 V_b[512]
// Output: y[8192,512] ++ h_final[2048]
// ---------------------------------------------------------------------------
extern "C" void kernel_launch(void* const* d_in, const int* in_sizes, int n_in,
                              void* d_out, int out_size)
{
    (void)in_sizes; (void)n_in; (void)out_size;
    const float* input  = (const float*)d_in[0];
    const float* hidden = (const float*)d_in[1];
    const float* U_w    = (const float*)d_in[2];
    const float* U_b    = (const float*)d_in[3];
    const float* W_w    = (const float*)d_in[4];
    const float* W_b    = (const float*)d_in[5];
    const float* V_w    = (const float*)d_in[6];
    const float* V_b    = (const float*)d_in[7];
    float* out = (float*)d_out;

    float *pA, *pH;
    cudaGetSymbolAddress((void**)&pA, g_A);
    cudaGetSymbolAddress((void**)&pH, g_Hst);

    // 1) reset counter + h_0
    init_k<<<8, 256>>>(hidden);

    // 2) A = X U^T + U_b : [8192,2048]
    sgemm_tn_bias<<<dim3(HSZ / 128, SEQLEN / 128), 256>>>(
        input, U_w, U_b, pA, SEQLEN, HSZ, INSZ);

    // 3) sequential recurrence -> g_Hst rows 1..8192
    rnn_recur<<<NCTA, 256>>>(W_w, W_b);

    // 4) Z = H V^T + V_b : [8192,512]  (reuse g_A as Z; H rows 1..8192)
    sgemm_tn_bias<<<dim3(OSZ / 128, SEQLEN / 128), 256>>>(
        pH + HSZ, V_w, V_b, pA, SEQLEN, OSZ, HSZ);

    // 5) y = log_softmax(Z) ; h_final
    logsoftmax_k<<<SEQLEN / 4, 128>>>(pA, out);
    copy_hfinal<<<8, 256>>>(out + (size_t)SEQLEN * OSZ);
}

// round 15
// speedup vs baseline: 3.0793x; 1.0040x over previous
#include <cuda_runtime.h>
#include <math.h>

// Problem dims
#define SEQLEN 8192
#define INSZ   512
#define HSZ    2048
#define OSZ    512

// Recurrence: 128 CTAs x 16 rows, 256 threads. Warp w (0..7) owns rows
// 2w, 2w+1. Lane l covers h/W elements 128j+4l..+3 (coalesced float4).
#define NCTA 128
#define RPC  16

// Scratch (device globals: allocation-free rule)
__device__ float    g_A[(size_t)SEQLEN * HSZ];         // U x_t + U_b ; reused as Z
__device__ float    g_Hst[(size_t)(SEQLEN + 1) * HSZ]; // h_0 .. h_8192
__device__ unsigned g_ctr;                             // single release counter

// ---------------------------------------------------------------------------
// PTX helpers
// ---------------------------------------------------------------------------
static __device__ __forceinline__ unsigned ld_acq(const unsigned* p) {
    unsigned v;
    asm volatile("ld.acquire.gpu.global.u32 %0, [%1];" : "=r"(v) : "l"(p));
    return v;
}
static __device__ __forceinline__ void red_rel_add(unsigned* p, unsigned v) {
    asm volatile("red.release.gpu.global.add.u32 [%0], %1;" :: "l"(p), "r"(v));
}
// packed f32x2 FMA: acc.{lo,hi} += a*b  (Blackwell; 2x fp32 rate)
static __device__ __forceinline__ void fma2(unsigned long long& acc,
                                            float a0, float a1, float b0, float b1) {
    asm("{\n\t"
        ".reg .b64 ta, tb;\n\t"
        "mov.b64 ta, {%1, %2};\n\t"
        "mov.b64 tb, {%3, %4};\n\t"
        "fma.rn.f32x2 %0, ta, tb, %0;\n\t"
        "}"
        : "+l"(acc) : "f"(a0), "f"(a1), "f"(b0), "f"(b1));
}
static __device__ __forceinline__ float unpack_sum(unsigned long long acc) {
    float lo, hi;
    asm("mov.b64 {%0, %1}, %2;" : "=f"(lo), "=f"(hi) : "l"(acc));
    return lo + hi;
}
static __device__ __forceinline__ void unpack2(unsigned long long acc,
                                               float& lo, float& hi) {
    asm("mov.b64 {%0, %1}, %2;" : "=f"(lo), "=f"(hi) : "l"(acc));
}
// tanh(x) = 1 - 2/(e^{2x}+1): MUFU ex2 + approx div (validated rel_err 1.1e-6)
static __device__ __forceinline__ float fast_tanh(float x) {
    float e = __expf(2.f * x);
    return 1.f - __fdividef(2.f, e + 1.f);
}

// ---------------------------------------------------------------------------
// Init: reset counter, load h_0
// ---------------------------------------------------------------------------
__global__ void init_k(const float* __restrict__ hidden) {
    int i = blockIdx.x * blockDim.x + threadIdx.x;
    if (i == 0) g_ctr = 0;
    if (i < HSZ) g_Hst[i] = hidden[i];
}

// ---------------------------------------------------------------------------
// SGEMM: C[M,N] = A[M,K] * B[N,K]^T + bias[N]   (row-major)
// Inner product via packed fma.rn.f32x2: 32 packed FMA per k-step instead of
// 64 scalar FFMA (this kernel is fma-issue-bound: fma=45.6%, issue=56%).
// acc[i][j2] packs columns {2*j2, 2*j2+1}; same register count as before.
// ---------------------------------------------------------------------------
__global__ __launch_bounds__(256) void sgemm_tn_bias(
    const float* __restrict__ A, const float* __restrict__ B,
    const float* __restrict__ bias, float* __restrict__ C,
    int M, int N, int K)
{
    __shared__ float As[8][128];
    __shared__ float Bs[8][128];
    const int tid  = threadIdx.x;
    const int tx   = tid & 15;
    const int ty   = tid >> 4;
    const int lrow = tid >> 1;
    const int lcol = (tid & 1) * 4;

    const float* Ap = A + (size_t)(blockIdx.y * 128 + lrow) * K + lcol;
    const float* Bp = B + (size_t)(blockIdx.x * 128 + lrow) * K + lcol;

    unsigned long long acc[8][4];
    #pragma unroll
    for (int i = 0; i < 8; ++i)
        #pragma unroll
        for (int j = 0; j < 4; ++j) acc[i][j] = 0ull;

    for (int k0 = 0; k0 < K; k0 += 8) {
        float4 a4 = *(const float4*)(Ap + k0);
        float4 b4 = *(const float4*)(Bp + k0);
        As[lcol + 0][lrow] = a4.x; As[lcol + 1][lrow] = a4.y;
        As[lcol + 2][lrow] = a4.z; As[lcol + 3][lrow] = a4.w;
        Bs[lcol + 0][lrow] = b4.x; Bs[lcol + 1][lrow] = b4.y;
        Bs[lcol + 2][lrow] = b4.z; Bs[lcol + 3][lrow] = b4.w;
        __syncthreads();
        #pragma unroll
        for (int k = 0; k < 8; ++k) {
            float ar[8], br[8];
            *(float4*)&ar[0] = *(const float4*)&As[k][ty * 8];
            *(float4*)&ar[4] = *(const float4*)&As[k][ty * 8 + 4];
            *(float4*)&br[0] = *(const float4*)&Bs[k][tx * 8];
            *(float4*)&br[4] = *(const float4*)&Bs[k][tx * 8 + 4];
            #pragma unroll
            for (int i = 0; i < 8; ++i)
                #pragma unroll
                for (int j = 0; j < 4; ++j)
                    fma2(acc[i][j], ar[i], ar[i], br[2 * j], br[2 * j + 1]);
        }
        __syncthreads();
    }

    const int cm = blockIdx.y * 128 + ty * 8;
    const int cn = blockIdx.x * 128 + tx * 8;
    float bv[8];
    #pragma unroll
    for (int j = 0; j < 8; ++j) bv[j] = bias[cn + j];
    #pragma unroll
    for (int i = 0; i < 8; ++i) {
        float c[8];
        #pragma unroll
        for (int j = 0; j < 4; ++j)
            unpack2(acc[i][j], c[2 * j], c[2 * j + 1]);
        float4 o0, o1;
        o0.x = c[0] + bv[0]; o0.y = c[1] + bv[1];
        o0.z = c[2] + bv[2]; o0.w = c[3] + bv[3];
        o1.x = c[4] + bv[4]; o1.y = c[5] + bv[5];
        o1.z = c[6] + bv[6]; o1.w = c[7] + bv[7];
        *(float4*)(C + (size_t)(cm + i) * N + cn)     = o0;
        *(float4*)(C + (size_t)(cm + i) * N + cn + 4) = o1;
    }
}

// ---------------------------------------------------------------------------
// Persistent recurrence: h_{i+1} = tanh(A[i] + W h_i + W_b)
// BYTE-IDENTICAL to the passing R14 kernel (tid0 poll -> bar -> compute ->
// bar -> tid0 release; chunked loads; W in registers).
// ---------------------------------------------------------------------------
__global__ __launch_bounds__(256, 1) void rnn_recur(
    const float* __restrict__ W, const float* __restrict__ Wb)
{
    const int tid  = threadIdx.x;
    const int cta  = blockIdx.x;
    const int warp = tid >> 5;     // 0..7
    const int lane = tid & 31;
    const int grow0 = cta * RPC + 2 * warp;      // this warp's first row

    float4 w0[16], w1[16];
    {
        const float4* W0 = (const float4*)(W + (size_t)grow0 * HSZ);
        const float4* W1 = (const float4*)(W + (size_t)(grow0 + 1) * HSZ);
        #pragma unroll
        for (int j = 0; j < 16; ++j) { w0[j] = W0[32 * j + lane]; w1[j] = W1[32 * j + lane]; }
    }
    float2 wb = make_float2(0.f, 0.f);
    if (lane == 0) wb = *(const float2*)(Wb + grow0);

    for (int i = 0; i < SEQLEN; ++i) {
        float2 av = make_float2(0.f, 0.f);
        if (lane == 0) av = *(const float2*)(g_A + (size_t)i * HSZ + grow0);

        if (i > 0) {
            if (tid == 0) {
                const unsigned target = (unsigned)i * NCTA;
                while (ld_acq(&g_ctr) < target) { }
            }
            __syncthreads();
        }

        const float4* hp = (const float4*)(g_Hst + (size_t)i * HSZ);
        unsigned long long a0 = 0ull, b0 = 0ull, a1 = 0ull, b1 = 0ull;
        #pragma unroll
        for (int c = 0; c < 2; ++c) {
            float4 hb[8];
            #pragma unroll
            for (int j = 0; j < 8; ++j) hb[j] = hp[32 * (c * 8 + j) + lane];
            #pragma unroll
            for (int j = 0; j < 8; ++j) {
                const int idx = c * 8 + j;
                fma2(a0, hb[j].x, hb[j].y, w0[idx].x, w0[idx].y);
                fma2(b0, hb[j].z, hb[j].w, w0[idx].z, w0[idx].w);
                fma2(a1, hb[j].x, hb[j].y, w1[idx].x, w1[idx].y);
                fma2(b1, hb[j].z, hb[j].w, w1[idx].z, w1[idx].w);
            }
        }
        float p0 = unpack_sum(a0) + unpack_sum(b0);
        float p1 = unpack_sum(a1) + unpack_sum(b1);

        #pragma unroll
        for (int o = 16; o > 0; o >>= 1) {
            p0 += __shfl_xor_sync(0xffffffffu, p0, o);
            p1 += __shfl_xor_sync(0xffffffffu, p1, o);
        }

        if (lane == 0) {
            float h0 = fast_tanh(p0 + av.x + wb.x);
            float h1 = fast_tanh(p1 + av.y + wb.y);
            *(float2*)(g_Hst + (size_t)(i + 1) * HSZ + grow0) = make_float2(h0, h1);
        }
        __syncthreads();
        if (tid == 0) red_rel_add(&g_ctr, 1u);
    }
}

// ---------------------------------------------------------------------------
// log_softmax over rows of Z [SEQLEN, OSZ], one warp per row
// ---------------------------------------------------------------------------
__global__ __launch_bounds__(128) void logsoftmax_k(
    const float* __restrict__ Z, float* __restrict__ Y)
{
    int warp = (blockIdx.x * blockDim.x + threadIdx.x) >> 5;
    int lane = threadIdx.x & 31;
    if (warp >= SEQLEN) return;
    const float* z = Z + (size_t)warp * OSZ;
    float v[16];
    float m = -INFINITY;
    #pragma unroll
    for (int j = 0; j < 16; ++j) {
        v[j] = z[lane + 32 * j];
        m = fmaxf(m, v[j]);
    }
    #pragma unroll
    for (int o = 16; o > 0; o >>= 1) m = fmaxf(m, __shfl_xor_sync(~0u, m, o));
    float s = 0.f;
    #pragma unroll
    for (int j = 0; j < 16; ++j) s += __expf(v[j] - m);
    #pragma unroll
    for (int o = 16; o > 0; o >>= 1) s += __shfl_xor_sync(~0u, s, o);
    float lse = m + __logf(s);
    float* y = Y + (size_t)warp * OSZ;
    #pragma unroll
    for (int j = 0; j < 16; ++j) y[lane + 32 * j] = v[j] - lse;
}

__global__ void copy_hfinal(float* __restrict__ out) {
    int i = blockIdx.x * blockDim.x + threadIdx.x;
    if (i < HSZ) out[i] = g_Hst[(size_t)SEQLEN * HSZ + i];
}

// ---------------------------------------------------------------------------
// kernel_launch
// Inputs: 0 input[8192,512] 1 hidden[1,2048] 2 U_w[2048,512] 3 U_b[2048]
//         4 W_w[2048,2048]  5 W_b[2048]      6 V_w[512,2048]  7 V_b[512]
// Output: y[8192,512] ++ h_final[2048]
// ---------------------------------------------------------------------------
extern "C" void kernel_launch(void* const* d_in, const int* in_sizes, int n_in,
                              void* d_out, int out_size)
{
    (void)in_sizes; (void)n_in; (void)out_size;
    const float* input  = (const float*)d_in[0];
    const float* hidden = (const float*)d_in[1];
    const float* U_w    = (const float*)d_in[2];
    const float* U_b    = (const float*)d_in[3];
    const float* W_w    = (const float*)d_in[4];
    const float* W_b    = (const float*)d_in[5];
    const float* V_w    = (const float*)d_in[6];
    const float* V_b    = (const float*)d_in[7];
    float* out = (float*)d_out;

    float *pA, *pH;
    cudaGetSymbolAddress((void**)&pA, g_A);
    cudaGetSymbolAddress((void**)&pH, g_Hst);

    // 1) reset counter + h_0
    init_k<<<8, 256>>>(hidden);

    // 2) A = X U^T + U_b : [8192,2048]
    sgemm_tn_bias<<<dim3(HSZ / 128, SEQLEN / 128), 256>>>(
        input, U_w, U_b, pA, SEQLEN, HSZ, INSZ);

    // 3) sequential recurrence -> g_Hst rows 1..8192
    rnn_recur<<<NCTA, 256>>>(W_w, W_b);

    // 4) Z = H V^T + V_b : [8192,512]  (reuse g_A as Z; H rows 1..8192)
    sgemm_tn_bias<<<dim3(OSZ / 128, SEQLEN / 128), 256>>>(
        pH + HSZ, V_w, V_b, pA, SEQLEN, OSZ, HSZ);

    // 5) y = log_softmax(Z) ; h_final
    logsoftmax_k<<<SEQLEN / 4, 128>>>(pA, out);
    copy_hfinal<<<8, 256>>>(out + (size_t)SEQLEN * OSZ);
}

// round 17
// speedup vs baseline: 3.1536x; 1.0241x over previous
#include <cuda_runtime.h>
#include <math.h>

// Problem dims
#define SEQLEN 8192
#define INSZ   512
#define HSZ    2048
#define OSZ    512

// Recurrence: 128 CTAs x 16 rows, 256 threads (8 warps) — R14's proven shape.
// Warp w owns rows 2w, 2w+1. Pre-barrier: each warp computes its rows'
// input projection av = x_i·U + U_b from SMEM-resident U (hidden under the
// tid0 poll + inter-CTA skew). Post-barrier: R14's h-matvec, chunked 4x4.
#define NCTA 128
#define RPC  16

// Scratch (device globals: allocation-free rule)
__device__ float    g_A[(size_t)SEQLEN * HSZ];         // Z = H V^T + V_b (GEMM2 out)
__device__ float    g_Hst[(size_t)(SEQLEN + 1) * HSZ]; // h_0 .. h_8192
__device__ unsigned g_ctr;                             // single release counter

// ---------------------------------------------------------------------------
// PTX helpers
// ---------------------------------------------------------------------------
static __device__ __forceinline__ unsigned ld_acq(const unsigned* p) {
    unsigned v;
    asm volatile("ld.acquire.gpu.global.u32 %0, [%1];" : "=r"(v) : "l"(p));
    return v;
}
static __device__ __forceinline__ void red_rel_add(unsigned* p, unsigned v) {
    asm volatile("red.release.gpu.global.add.u32 [%0], %1;" :: "l"(p), "r"(v));
}
// packed f32x2 FMA: acc.{lo,hi} += a*b  (Blackwell; 2x fp32 rate)
static __device__ __forceinline__ void fma2(unsigned long long& acc,
                                            float a0, float a1, float b0, float b1) {
    asm("{\n\t"
        ".reg .b64 ta, tb;\n\t"
        "mov.b64 ta, {%1, %2};\n\t"
        "mov.b64 tb, {%3, %4};\n\t"
        "fma.rn.f32x2 %0, ta, tb, %0;\n\t"
        "}"
        : "+l"(acc) : "f"(a0), "f"(a1), "f"(b0), "f"(b1));
}
static __device__ __forceinline__ float unpack_sum(unsigned long long acc) {
    float lo, hi;
    asm("mov.b64 {%0, %1}, %2;" : "=f"(lo), "=f"(hi) : "l"(acc));
    return lo + hi;
}
static __device__ __forceinline__ void unpack2(unsigned long long acc,
                                               float& lo, float& hi) {
    asm("mov.b64 {%0, %1}, %2;" : "=f"(lo), "=f"(hi) : "l"(acc));
}
// tanh(x) = 1 - 2/(e^{2x}+1): MUFU ex2 + approx div (validated rel_err 1.1e-6)
static __device__ __forceinline__ float fast_tanh(float x) {
    float e = __expf(2.f * x);
    return 1.f - __fdividef(2.f, e + 1.f);
}

// ---------------------------------------------------------------------------
// Init: reset counter, load h_0
// ---------------------------------------------------------------------------
__global__ void init_k(const float* __restrict__ hidden) {
    int i = blockIdx.x * blockDim.x + threadIdx.x;
    if (i == 0) g_ctr = 0;
    if (i < HSZ) g_Hst[i] = hidden[i];
}

// ---------------------------------------------------------------------------
// SGEMM (packed f32x2): C[M,N] = A[M,K] * B[N,K]^T + bias[N]  (row-major)
// Used only for Z = H V^T + V_b.
// ---------------------------------------------------------------------------
__global__ __launch_bounds__(256) void sgemm_tn_bias(
    const float* __restrict__ A, const float* __restrict__ B,
    const float* __restrict__ bias, float* __restrict__ C,
    int M, int N, int K)
{
    __shared__ float As[8][128];
    __shared__ float Bs[8][128];
    const int tid  = threadIdx.x;
    const int tx   = tid & 15;
    const int ty   = tid >> 4;
    const int lrow = tid >> 1;
    const int lcol = (tid & 1) * 4;

    const float* Ap = A + (size_t)(blockIdx.y * 128 + lrow) * K + lcol;
    const float* Bp = B + (size_t)(blockIdx.x * 128 + lrow) * K + lcol;

    unsigned long long acc[8][4];
    #pragma unroll
    for (int i = 0; i < 8; ++i)
        #pragma unroll
        for (int j = 0; j < 4; ++j) acc[i][j] = 0ull;

    for (int k0 = 0; k0 < K; k0 += 8) {
        float4 a4 = *(const float4*)(Ap + k0);
        float4 b4 = *(const float4*)(Bp + k0);
        As[lcol + 0][lrow] = a4.x; As[lcol + 1][lrow] = a4.y;
        As[lcol + 2][lrow] = a4.z; As[lcol + 3][lrow] = a4.w;
        Bs[lcol + 0][lrow] = b4.x; Bs[lcol + 1][lrow] = b4.y;
        Bs[lcol + 2][lrow] = b4.z; Bs[lcol + 3][lrow] = b4.w;
        __syncthreads();
        #pragma unroll
        for (int k = 0; k < 8; ++k) {
            float ar[8], br[8];
            *(float4*)&ar[0] = *(const float4*)&As[k][ty * 8];
            *(float4*)&ar[4] = *(const float4*)&As[k][ty * 8 + 4];
            *(float4*)&br[0] = *(const float4*)&Bs[k][tx * 8];
            *(float4*)&br[4] = *(const float4*)&Bs[k][tx * 8 + 4];
            #pragma unroll
            for (int i = 0; i < 8; ++i)
                #pragma unroll
                for (int j = 0; j < 4; ++j)
                    fma2(acc[i][j], ar[i], ar[i], br[2 * j], br[2 * j + 1]);
        }
        __syncthreads();
    }

    const int cm = blockIdx.y * 128 + ty * 8;
    const int cn = blockIdx.x * 128 + tx * 8;
    float bv[8];
    #pragma unroll
    for (int j = 0; j < 8; ++j) bv[j] = bias[cn + j];
    #pragma unroll
    for (int i = 0; i < 8; ++i) {
        float c[8];
        #pragma unroll
        for (int j = 0; j < 4; ++j)
            unpack2(acc[i][j], c[2 * j], c[2 * j + 1]);
        float4 o0, o1;
        o0.x = c[0] + bv[0]; o0.y = c[1] + bv[1];
        o0.z = c[2] + bv[2]; o0.w = c[3] + bv[3];
        o1.x = c[4] + bv[4]; o1.y = c[5] + bv[5];
        o1.z = c[6] + bv[6]; o1.w = c[7] + bv[7];
        *(float4*)(C + (size_t)(cm + i) * N + cn)     = o0;
        *(float4*)(C + (size_t)(cm + i) * N + cn + 4) = o1;
    }
}

// ---------------------------------------------------------------------------
// Persistent recurrence with fused input projection (256 threads, 8 warps):
//   h_{i+1} = tanh(x_i U^T + U_b + W h_i + W_b)
// Pre-barrier: av from SMEM U (hidden under poll+skew). Sync skeleton =
// R14's proven protocol exactly. h loop chunked 4x4 float4 to keep regs <256.
// ---------------------------------------------------------------------------
__global__ __launch_bounds__(256, 1) void rnn_recur(
    const float* __restrict__ W, const float* __restrict__ Wb,
    const float* __restrict__ U, const float* __restrict__ Ub,
    const float* __restrict__ X)
{
    const int tid  = threadIdx.x;
    const int cta  = blockIdx.x;
    const int warp = tid >> 5;     // 0..7
    const int lane = tid & 31;
    const int grow0 = cta * RPC + 2 * warp;      // this warp's first row

    __shared__ float U_s[RPC * INSZ];   // this CTA's 16 U rows (32 KB)
    {
        const float4* Ug = (const float4*)(U + (size_t)cta * RPC * INSZ);
        float4* Us4 = (float4*)U_s;
        #pragma unroll 4
        for (int t = tid; t < RPC * INSZ / 4; t += 256) Us4[t] = Ug[t];
    }

    // W slices in registers: rows grow0, grow0+1 (128 floats/thread)
    float4 w0[16], w1[16];
    {
        const float4* W0 = (const float4*)(W + (size_t)grow0 * HSZ);
        const float4* W1 = (const float4*)(W + (size_t)(grow0 + 1) * HSZ);
        #pragma unroll
        for (int j = 0; j < 16; ++j) { w0[j] = W0[32 * j + lane]; w1[j] = W1[32 * j + lane]; }
    }
    float2 wb = make_float2(0.f, 0.f);
    if (lane == 0) {
        float2 wv = *(const float2*)(Wb + grow0);
        float2 uv = *(const float2*)(Ub + grow0);
        wb = make_float2(wv.x + uv.x, wv.y + uv.y);   // fold both biases
    }
    __syncthreads();    // U_s staged

    for (int i = 0; i < SEQLEN; ++i) {
        // --- pre-barrier: input projection for this warp's two rows ---
        // (independent of h_i; executes while tid0 polls / other CTAs finish)
        float2 av;
        {
            const float4* xp = (const float4*)(X + (size_t)i * INSZ);
            const float4* u0 = (const float4*)(U_s + (size_t)(2 * warp) * INSZ);
            const float4* u1 = (const float4*)(U_s + (size_t)(2 * warp + 1) * INSZ);
            unsigned long long ax = 0ull, bx = 0ull, ay = 0ull, by = 0ull;
            #pragma unroll
            for (int c = 0; c < 4; ++c) {
                float4 xv  = xp[lane + 32 * c];
                float4 uv0 = u0[lane + 32 * c];
                float4 uv1 = u1[lane + 32 * c];
                fma2(ax, xv.x, xv.y, uv0.x, uv0.y);
                fma2(bx, xv.z, xv.w, uv0.z, uv0.w);
                fma2(ay, xv.x, xv.y, uv1.x, uv1.y);
                fma2(by, xv.z, xv.w, uv1.z, uv1.w);
            }
            float q0 = unpack_sum(ax) + unpack_sum(bx);
            float q1 = unpack_sum(ay) + unpack_sum(by);
            #pragma unroll
            for (int o = 16; o > 0; o >>= 1) {
                q0 += __shfl_xor_sync(0xffffffffu, q0, o);
                q1 += __shfl_xor_sync(0xffffffffu, q1, o);
            }
            av = make_float2(q0, q1);
        }

        // --- wait for all CTAs to have published h_i (R14 protocol) ---
        if (i > 0) {
            if (tid == 0) {
                const unsigned target = (unsigned)i * NCTA;
                while (ld_acq(&g_ctr) < target) { }
            }
            __syncthreads();
        }

        // --- recurrent matvec, chunked 4x4 float4 (low reg pressure) ---
        const float4* hp = (const float4*)(g_Hst + (size_t)i * HSZ);
        unsigned long long a0 = 0ull, b0 = 0ull, a1 = 0ull, b1 = 0ull;
        #pragma unroll
        for (int c = 0; c < 4; ++c) {
            float4 hb[4];
            #pragma unroll
            for (int j = 0; j < 4; ++j) hb[j] = hp[32 * (c * 4 + j) + lane];
            #pragma unroll
            for (int j = 0; j < 4; ++j) {
                const int idx = c * 4 + j;
                fma2(a0, hb[j].x, hb[j].y, w0[idx].x, w0[idx].y);
                fma2(b0, hb[j].z, hb[j].w, w0[idx].z, w0[idx].w);
                fma2(a1, hb[j].x, hb[j].y, w1[idx].x, w1[idx].y);
                fma2(b1, hb[j].z, hb[j].w, w1[idx].z, w1[idx].w);
            }
        }
        float p0 = unpack_sum(a0) + unpack_sum(b0);
        float p1 = unpack_sum(a1) + unpack_sum(b1);

        #pragma unroll
        for (int o = 16; o > 0; o >>= 1) {
            p0 += __shfl_xor_sync(0xffffffffu, p0, o);
            p1 += __shfl_xor_sync(0xffffffffu, p1, o);
        }

        if (lane == 0) {
            float h0 = fast_tanh(p0 + av.x + wb.x);
            float h1 = fast_tanh(p1 + av.y + wb.y);
            *(float2*)(g_Hst + (size_t)(i + 1) * HSZ + grow0) = make_float2(h0, h1);
        }
        __syncthreads();          // all 16 rows of this CTA stored
        if (tid == 0) red_rel_add(&g_ctr, 1u);   // publish
    }
}

// ---------------------------------------------------------------------------
// log_softmax over rows of Z [SEQLEN, OSZ], one warp per row
// ---------------------------------------------------------------------------
__global__ __launch_bounds__(128) void logsoftmax_k(
    const float* __restrict__ Z, float* __restrict__ Y)
{
    int warp = (blockIdx.x * blockDim.x + threadIdx.x) >> 5;
    int lane = threadIdx.x & 31;
    if (warp >= SEQLEN) return;
    const float* z = Z + (size_t)warp * OSZ;
    float v[16];
    float m = -INFINITY;
    #pragma unroll
    for (int j = 0; j < 16; ++j) {
        v[j] = z[lane + 32 * j];
        m = fmaxf(m, v[j]);
    }
    #pragma unroll
    for (int o = 16; o > 0; o >>= 1) m = fmaxf(m, __shfl_xor_sync(~0u, m, o));
    float s = 0.f;
    #pragma unroll
    for (int j = 0; j < 16; ++j) s += __expf(v[j] - m);
    #pragma unroll
    for (int o = 16; o > 0; o >>= 1) s += __shfl_xor_sync(~0u, s, o);
    float lse = m + __logf(s);
    float* y = Y + (size_t)warp * OSZ;
    #pragma unroll
    for (int j = 0; j < 16; ++j) y[lane + 32 * j] = v[j] - lse;
}

__global__ void copy_hfinal(float* __restrict__ out) {
    int i = blockIdx.x * blockDim.x + threadIdx.x;
    if (i < HSZ) out[i] = g_Hst[(size_t)SEQLEN * HSZ + i];
}

// ---------------------------------------------------------------------------
// kernel_launch
// Inputs: 0 input[8192,512] 1 hidden[1,2048] 2 U_w[2048,512] 3 U_b[2048]
//         4 W_w[2048,2048]  5 W_b[2048]      6 V_w[512,2048]  7 V_b[512]
// Output: y[8192,512] ++ h_final[2048]
// ---------------------------------------------------------------------------
extern "C" void kernel_launch(void* const* d_in, const int* in_sizes, int n_in,
                              void* d_out, int out_size)
{
    (void)in_sizes; (void)n_in; (void)out_size;
    const float* input  = (const float*)d_in[0];
    const float* hidden = (const float*)d_in[1];
    const float* U_w    = (const float*)d_in[2];
    const float* U_b    = (const float*)d_in[3];
    const float* W_w    = (const float*)d_in[4];
    const float* W_b    = (const float*)d_in[5];
    const float* V_w    = (const float*)d_in[6];
    const float* V_b    = (const float*)d_in[7];
    float* out = (float*)d_out;

    float *pA, *pH;
    cudaGetSymbolAddress((void**)&pA, g_A);
    cudaGetSymbolAddress((void**)&pH, g_Hst);

    // 1) reset counter + h_0
    init_k<<<8, 256>>>(hidden);

    // 2) recurrence with fused input projection (GEMM1 eliminated)
    rnn_recur<<<NCTA, 256>>>(W_w, W_b, U_w, U_b, input);

    // 3) Z = H V^T + V_b : [8192,512]  (g_A as Z; H rows 1..8192)
    sgemm_tn_bias<<<dim3(OSZ / 128, SEQLEN / 128), 256>>>(
        pH + HSZ, V_w, V_b, pA, SEQLEN, OSZ, HSZ);

    // 4) y = log_softmax(Z) ; h_final
    logsoftmax_k<<<SEQLEN / 4, 128>>>(pA, out);
    copy_hfinal<<<8, 256>>>(out + (size_t)SEQLEN * OSZ);
}